// round 1
// baseline (speedup 1.0000x reference)
#include <cuda_runtime.h>
#include <math.h>

#define S_LEN 2048
#define D_MODEL 2048
#define NH 16
#define HDIM 128
#define CQ_DIM 96
#define CKV_DIM 512

// ---------------- scratch (static device memory; no allocations) ----------------
__device__ float g_cq[S_LEN * CQ_DIM];
__device__ float g_ckv[S_LEN * CKV_DIM];
__device__ float g_q[S_LEN * NH * HDIM];
__device__ float g_k[S_LEN * NH * HDIM];
__device__ float g_v[S_LEN * NH * HDIM];
__device__ float g_attn[S_LEN * NH * HDIM];

// ---------------- GEMM: C[M,N] = A[M,K] @ B[N,K]^T + bias[N] ----------------
// 128x128 tile, BK=16, 256 threads, 8x8 per-thread microtile.
// Requirements used here: M % 128 == 0, K % 16 == 0 (true for all call sites).
__global__ __launch_bounds__(256) void sgemm_bias_kernel(
    const float* __restrict__ A, const float* __restrict__ B,
    const float* __restrict__ bias, float* __restrict__ C,
    int M, int N, int K)
{
    __shared__ float As[16][128];
    __shared__ float Bs[16][128];

    const int tid = threadIdx.x;
    const int tx = tid & 15;
    const int ty = tid >> 4;
    const int bm0 = blockIdx.y * 128;
    const int bn0 = blockIdx.x * 128;

    float acc[8][8];
#pragma unroll
    for (int i = 0; i < 8; i++)
#pragma unroll
        for (int j = 0; j < 8; j++) acc[i][j] = 0.f;

    for (int k0 = 0; k0 < K; k0 += 16) {
        // load A tile: 128 rows x 16 cols = 512 float4, 2 per thread
#pragma unroll
        for (int i = 0; i < 2; i++) {
            int f = tid + i * 256;
            int row = f >> 2;
            int kc = (f & 3) << 2;
            float4 v = *(const float4*)&A[(size_t)(bm0 + row) * K + k0 + kc];
            As[kc + 0][row] = v.x;
            As[kc + 1][row] = v.y;
            As[kc + 2][row] = v.z;
            As[kc + 3][row] = v.w;
        }
        // load B tile (guard N)
#pragma unroll
        for (int i = 0; i < 2; i++) {
            int f = tid + i * 256;
            int n = f >> 2;
            int kc = (f & 3) << 2;
            float4 v = make_float4(0.f, 0.f, 0.f, 0.f);
            if (bn0 + n < N)
                v = *(const float4*)&B[(size_t)(bn0 + n) * K + k0 + kc];
            Bs[kc + 0][n] = v.x;
            Bs[kc + 1][n] = v.y;
            Bs[kc + 2][n] = v.z;
            Bs[kc + 3][n] = v.w;
        }
        __syncthreads();

#pragma unroll
        for (int k = 0; k < 16; k++) {
            float a[8], b[8];
            float4 a0 = *(float4*)&As[k][ty * 8];
            float4 a1 = *(float4*)&As[k][ty * 8 + 4];
            float4 b0 = *(float4*)&Bs[k][tx * 8];
            float4 b1 = *(float4*)&Bs[k][tx * 8 + 4];
            a[0] = a0.x; a[1] = a0.y; a[2] = a0.z; a[3] = a0.w;
            a[4] = a1.x; a[5] = a1.y; a[6] = a1.z; a[7] = a1.w;
            b[0] = b0.x; b[1] = b0.y; b[2] = b0.z; b[3] = b0.w;
            b[4] = b1.x; b[5] = b1.y; b[6] = b1.z; b[7] = b1.w;
#pragma unroll
            for (int i = 0; i < 8; i++)
#pragma unroll
                for (int j = 0; j < 8; j++)
                    acc[i][j] = fmaf(a[i], b[j], acc[i][j]);
        }
        __syncthreads();
    }

#pragma unroll
    for (int i = 0; i < 8; i++) {
        int row = bm0 + ty * 8 + i;
#pragma unroll
        for (int j = 0; j < 8; j++) {
            int col = bn0 + tx * 8 + j;
            if (col < N)
                C[(size_t)row * N + col] = acc[i][j] + bias[col];
        }
    }
}

// ---------------- RoPE on q (with 1/sqrt(HD) scale) and k ----------------
__global__ __launch_bounds__(256) void rope_kernel(
    float* __restrict__ q, float* __restrict__ k,
    const float* __restrict__ cosb, const float* __restrict__ sinb)
{
    int idx = blockIdx.x * blockDim.x + threadIdx.x;  // 0 .. S*H*64-1
    int dh = idx & 63;
    int t = idx >> 6;
    int h = t & (NH - 1);
    int s = t >> 4;
    if (s >= S_LEN) return;

    float c1 = cosb[s * HDIM + dh];
    float s1 = sinb[s * HDIM + dh];
    float c2 = cosb[s * HDIM + dh + 64];
    float s2 = sinb[s * HDIM + dh + 64];

    size_t base = (size_t)s * (NH * HDIM) + h * HDIM + dh;
    const float sc = 0.08838834764831845f;  // 1/sqrt(128)

    float q1 = q[base], q2 = q[base + 64];
    q[base]      = (q1 * c1 - q2 * s1) * sc;
    q[base + 64] = (q2 * c2 + q1 * s2) * sc;

    float k1 = k[base], k2 = k[base + 64];
    k[base]      = k1 * c1 - k2 * s1;
    k[base + 64] = k2 * c2 + k1 * s2;
}

// ---------------- Flash attention (non-causal), fp32 ----------------
// grid = (S/64, H), 256 threads. Br = Bc = 64, full HD=128 in smem.
#define LDQ 132   // padded row stride for 128-wide tiles (keeps 16B alignment)
#define LDP 68    // padded row stride for P tile
#define FLASH_SMEM_BYTES ((3 * 64 * LDQ + 64 * LDP) * 4)

__global__ __launch_bounds__(256) void flash_kernel(
    const float* __restrict__ Qg, const float* __restrict__ Kg,
    const float* __restrict__ Vg, float* __restrict__ Og)
{
    extern __shared__ float sm[];
    float* Qs = sm;
    float* Ks = sm + 64 * LDQ;
    float* Vs = sm + 2 * 64 * LDQ;
    float* Ps = sm + 3 * 64 * LDQ;

    const int tid = threadIdx.x;
    const int tx = tid & 15;
    const int ty = tid >> 4;
    const int h = blockIdx.y;
    const int q0 = blockIdx.x * 64;

    // load Q tile [64][128]
#pragma unroll
    for (int i = 0; i < 8; i++) {
        int f = tid + i * 256;
        int row = f >> 5;
        int c = (f & 31) << 2;
        *(float4*)&Qs[row * LDQ + c] =
            *(const float4*)&Qg[(size_t)(q0 + row) * (NH * HDIM) + h * HDIM + c];
    }

    float o[4][8];
    float m_i[4], l_i[4];
#pragma unroll
    for (int i = 0; i < 4; i++) {
        m_i[i] = -1e30f;
        l_i[i] = 0.f;
#pragma unroll
        for (int j = 0; j < 8; j++) o[i][j] = 0.f;
    }

    for (int kv0 = 0; kv0 < S_LEN; kv0 += 64) {
        __syncthreads();  // protect Ks/Vs/Ps from previous iteration readers
#pragma unroll
        for (int i = 0; i < 8; i++) {
            int f = tid + i * 256;
            int row = f >> 5;
            int c = (f & 31) << 2;
            size_t g = (size_t)(kv0 + row) * (NH * HDIM) + h * HDIM + c;
            *(float4*)&Ks[row * LDQ + c] = *(const float4*)&Kg[g];
            *(float4*)&Vs[row * LDQ + c] = *(const float4*)&Vg[g];
        }
        __syncthreads();

        // S = Q K^T  (4x4 microtile per thread)
        float sa[4][4];
#pragma unroll
        for (int i = 0; i < 4; i++)
#pragma unroll
            for (int j = 0; j < 4; j++) sa[i][j] = 0.f;

#pragma unroll 8
        for (int k = 0; k < HDIM; k += 4) {
            float4 a[4], b[4];
#pragma unroll
            for (int i = 0; i < 4; i++)
                a[i] = *(float4*)&Qs[(ty * 4 + i) * LDQ + k];
#pragma unroll
            for (int j = 0; j < 4; j++)
                b[j] = *(float4*)&Ks[(tx * 4 + j) * LDQ + k];
#pragma unroll
            for (int i = 0; i < 4; i++)
#pragma unroll
                for (int j = 0; j < 4; j++) {
                    sa[i][j] = fmaf(a[i].x, b[j].x, sa[i][j]);
                    sa[i][j] = fmaf(a[i].y, b[j].y, sa[i][j]);
                    sa[i][j] = fmaf(a[i].z, b[j].z, sa[i][j]);
                    sa[i][j] = fmaf(a[i].w, b[j].w, sa[i][j]);
                }
        }

        // online softmax per row (rows are distributed across 16-lane groups)
#pragma unroll
        for (int i = 0; i < 4; i++) {
            float mx = fmaxf(fmaxf(sa[i][0], sa[i][1]), fmaxf(sa[i][2], sa[i][3]));
#pragma unroll
            for (int m = 1; m < 16; m <<= 1)
                mx = fmaxf(mx, __shfl_xor_sync(0xffffffffu, mx, m));
            float mnew = fmaxf(m_i[i], mx);
            float scale = __expf(m_i[i] - mnew);
            float sum = 0.f;
#pragma unroll
            for (int j = 0; j < 4; j++) {
                float p = __expf(sa[i][j] - mnew);
                sa[i][j] = p;
                sum += p;
            }
#pragma unroll
            for (int m = 1; m < 16; m <<= 1)
                sum += __shfl_xor_sync(0xffffffffu, sum, m);
            l_i[i] = l_i[i] * scale + sum;
            m_i[i] = mnew;
#pragma unroll
            for (int j = 0; j < 8; j++) o[i][j] *= scale;
#pragma unroll
            for (int j = 0; j < 4; j++)
                Ps[(ty * 4 + i) * LDP + tx * 4 + j] = sa[i][j];
        }
        __syncthreads();

        // O += P @ V
#pragma unroll 4
        for (int c = 0; c < 64; c++) {
            float p[4];
#pragma unroll
            for (int i = 0; i < 4; i++)
                p[i] = Ps[(ty * 4 + i) * LDP + c];
            float4 v0 = *(float4*)&Vs[c * LDQ + tx * 8];
            float4 v1 = *(float4*)&Vs[c * LDQ + tx * 8 + 4];
#pragma unroll
            for (int i = 0; i < 4; i++) {
                o[i][0] = fmaf(p[i], v0.x, o[i][0]);
                o[i][1] = fmaf(p[i], v0.y, o[i][1]);
                o[i][2] = fmaf(p[i], v0.z, o[i][2]);
                o[i][3] = fmaf(p[i], v0.w, o[i][3]);
                o[i][4] = fmaf(p[i], v1.x, o[i][4]);
                o[i][5] = fmaf(p[i], v1.y, o[i][5]);
                o[i][6] = fmaf(p[i], v1.z, o[i][6]);
                o[i][7] = fmaf(p[i], v1.w, o[i][7]);
            }
        }
    }

    // epilogue: O / l
#pragma unroll
    for (int i = 0; i < 4; i++) {
        float inv = 1.f / l_i[i];
        int row = q0 + ty * 4 + i;
        size_t base = (size_t)row * (NH * HDIM) + h * HDIM + tx * 8;
#pragma unroll
        for (int j = 0; j < 8; j++)
            Og[base + j] = o[i][j] * inv;
    }
}

// ---------------- launch ----------------
extern "C" void kernel_launch(void* const* d_in, const int* in_sizes, int n_in,
                              void* d_out, int out_size)
{
    const float* x        = (const float*)d_in[0];
    const float* rope_cos = (const float*)d_in[1];
    const float* rope_sin = (const float*)d_in[2];
    const float* wq_down  = (const float*)d_in[3];
    const float* bq_down  = (const float*)d_in[4];
    const float* wq_up    = (const float*)d_in[5];
    const float* bq_up    = (const float*)d_in[6];
    const float* wkv_down = (const float*)d_in[7];
    const float* bkv_down = (const float*)d_in[8];
    const float* wk_up    = (const float*)d_in[9];
    const float* bk_up    = (const float*)d_in[10];
    const float* wv_up    = (const float*)d_in[11];
    const float* bv_up    = (const float*)d_in[12];
    const float* wo       = (const float*)d_in[13];
    const float* bo       = (const float*)d_in[14];
    float* out = (float*)d_out;

    float *cq, *ckv, *q, *k, *v, *attn;
    cudaGetSymbolAddress((void**)&cq,   g_cq);
    cudaGetSymbolAddress((void**)&ckv,  g_ckv);
    cudaGetSymbolAddress((void**)&q,    g_q);
    cudaGetSymbolAddress((void**)&k,    g_k);
    cudaGetSymbolAddress((void**)&v,    g_v);
    cudaGetSymbolAddress((void**)&attn, g_attn);

    dim3 blk(256);

    // c_q = x @ wq_down^T + b            [2048, 96]
    sgemm_bias_kernel<<<dim3(1, 16), blk>>>(x, wq_down, bq_down, cq,
                                            S_LEN, CQ_DIM, D_MODEL);
    // q = c_q @ wq_up^T + b              [2048, 2048]
    sgemm_bias_kernel<<<dim3(16, 16), blk>>>(cq, wq_up, bq_up, q,
                                             S_LEN, NH * HDIM, CQ_DIM);
    // c_kv = x @ wkv_down^T + b          [2048, 512]
    sgemm_bias_kernel<<<dim3(4, 16), blk>>>(x, wkv_down, bkv_down, ckv,
                                            S_LEN, CKV_DIM, D_MODEL);
    // k = c_kv @ wk_up^T + b             [2048, 2048]
    sgemm_bias_kernel<<<dim3(16, 16), blk>>>(ckv, wk_up, bk_up, k,
                                             S_LEN, NH * HDIM, CKV_DIM);
    // v = c_kv @ wv_up^T + b             [2048, 2048]
    sgemm_bias_kernel<<<dim3(16, 16), blk>>>(ckv, wv_up, bv_up, v,
                                             S_LEN, NH * HDIM, CKV_DIM);

    // rope(q) * 1/sqrt(HD), rope(k)
    rope_kernel<<<(S_LEN * NH * 64) / 256, blk>>>(q, k, rope_cos, rope_sin);

    // attention
    cudaFuncSetAttribute(flash_kernel,
                         cudaFuncAttributeMaxDynamicSharedMemorySize,
                         FLASH_SMEM_BYTES);
    flash_kernel<<<dim3(S_LEN / 64, NH), blk, FLASH_SMEM_BYTES>>>(q, k, v, attn);

    // out = attn @ wo^T + bo             [2048, 2048]
    sgemm_bias_kernel<<<dim3(16, 16), blk>>>(attn, wo, bo, out,
                                             S_LEN, D_MODEL, D_MODEL);
}

// round 4
// speedup vs baseline: 3.8196x; 3.8196x over previous
#include <cuda_runtime.h>
#include <cstdint>

#define S_LEN 2048
#define D_MODEL 2048
#define NH 16
#define HDIM 128
#define CQ_DIM 96
#define CKV_DIM 512

// ---------------- scratch (static device memory; no allocations) ----------------
__device__ float g_cq[S_LEN * CQ_DIM];
__device__ float g_ckv[S_LEN * CKV_DIM];
__device__ float g_q[S_LEN * NH * HDIM];
__device__ float g_k[S_LEN * NH * HDIM];
__device__ float g_v[S_LEN * NH * HDIM];
__device__ float g_vt[S_LEN * NH * HDIM];
__device__ float g_attn[S_LEN * NH * HDIM];
__device__ float g_logits[(long long)NH * S_LEN * S_LEN]; // 256 MB
// rounded copies of external inputs
__device__ float g_x[S_LEN * D_MODEL];
__device__ float g_wqd[CQ_DIM * D_MODEL];
__device__ float g_wqu[(NH * HDIM) * CQ_DIM];
__device__ float g_wkvd[CKV_DIM * D_MODEL];
__device__ float g_wku[(NH * HDIM) * CKV_DIM];
__device__ float g_wvu[(NH * HDIM) * CKV_DIM];
__device__ float g_wo[D_MODEL * (NH * HDIM)];

// ---------------- helpers ----------------
__device__ __forceinline__ uint32_t smem_u32(const void* p) {
    uint32_t a;
    asm("{ .reg .u64 t; cvta.to.shared.u64 t, %1; cvt.u32.u64 %0, t; }" : "=r"(a) : "l"(p));
    return a;
}
__device__ __forceinline__ float rtf32(float x) {
    uint32_t u;
    asm("cvt.rna.tf32.f32 %0, %1;" : "=r"(u) : "f"(x));
    return __uint_as_float(u);
}
#define CP_ASYNC(dst, src, sz) \
    asm volatile("cp.async.cg.shared.global [%0], [%1], 16, %2;" \
        :: "r"(dst), "l"(src), "r"(sz) : "memory")
#define CP_COMMIT() asm volatile("cp.async.commit_group;" ::: "memory")
#define CP_WAIT(n)  asm volatile("cp.async.wait_group %0;" :: "n"(n) : "memory")

__device__ __forceinline__ void mma_u(float* c, const uint32_t* a, const uint32_t* b) {
    asm volatile(
        "mma.sync.aligned.m16n8k8.row.col.f32.tf32.tf32.f32 "
        "{%0,%1,%2,%3}, {%4,%5,%6,%7}, {%8,%9}, {%0,%1,%2,%3};"
        : "+f"(c[0]), "+f"(c[1]), "+f"(c[2]), "+f"(c[3])
        : "r"(a[0]), "r"(a[1]), "r"(a[2]), "r"(a[3]), "r"(b[0]), "r"(b[1]));
}
__device__ __forceinline__ void split3(float f, uint32_t& hi, uint32_t& lo) {
    asm("cvt.rna.tf32.f32 %0, %1;" : "=r"(hi) : "f"(f));
    float r = f - __uint_as_float(hi);
    asm("cvt.rna.tf32.f32 %0, %1;" : "=r"(lo) : "f"(r));
}

// ---------------- tf32 mma.sync GEMM: C = A[M,K] @ B[N,K]^T (+bias) ----------------
// BM=128, BN=128, BK=32, 256 threads, 2-stage cp.async.
// PREC=0: operands assumed pre-rounded to tf32 (RN), 1 mma per microtile step.
// PREC=1: operands raw fp32; hi/lo split, 3 mmas (tf32x3, ~fp32 accuracy).
#define LDT 36
#define TILE_FLOATS (128 * LDT)
#define STAGE_BYTES (2 * TILE_FLOATS * 4)
#define GEMM_SMEM (2 * STAGE_BYTES)

template <int PREC>
__global__ __launch_bounds__(256, 2) void gemm_mma(
    const float* __restrict__ Ab, const float* __restrict__ Bb,
    const float* __restrict__ bias, float* __restrict__ Cb,
    int N, int K, int lda, int ldb, int ldc,
    long long aBatch, long long bBatch, long long cBatch, int round_out)
{
    extern __shared__ char smem[];
    const uint32_t su = smem_u32(smem);

    const int tid = threadIdx.x;
    const int warp = tid >> 5;
    const int lane = tid & 31;
    const int wm = warp & 1;
    const int wn = warp >> 1;
    const float* A = Ab + (long long)blockIdx.z * aBatch;
    const float* B = Bb + (long long)blockIdx.z * bBatch;
    float* C = Cb + (long long)blockIdx.z * cBatch;
    const int bm0 = blockIdx.y * 128;
    const int bn0 = blockIdx.x * 128;

    int smoff[4];
    const float* aptr[4];
    const float* bptr[4];
    uint32_t bsz[4];
#pragma unroll
    for (int i = 0; i < 4; i++) {
        int idx = tid + i * 256;
        int r = idx >> 3;
        int c4 = idx & 7;
        smoff[i] = (r * LDT + c4 * 4) * 4;
        aptr[i] = A + (size_t)(bm0 + r) * lda + c4 * 4;
        bptr[i] = B + (size_t)(bn0 + r) * ldb + c4 * 4;
        bsz[i] = (bn0 + r < N) ? 16u : 0u;
    }

    float acc[4][4][4];
#pragma unroll
    for (int mt = 0; mt < 4; mt++)
#pragma unroll
        for (int nt = 0; nt < 4; nt++)
#pragma unroll
            for (int j = 0; j < 4; j++) acc[mt][nt][j] = 0.f;

    const int nsteps = K >> 5;
    {
        uint32_t sb = su;
#pragma unroll
        for (int i = 0; i < 4; i++) CP_ASYNC(sb + smoff[i], aptr[i], 16u);
#pragma unroll
        for (int i = 0; i < 4; i++) CP_ASYNC(sb + TILE_FLOATS * 4 + smoff[i], bptr[i], bsz[i]);
        CP_COMMIT();
    }

    for (int s = 0; s < nsteps; s++) {
        if (s + 1 < nsteps) {
            uint32_t sb = su + ((s + 1) & 1) * STAGE_BYTES;
            const int k0 = (s + 1) << 5;
#pragma unroll
            for (int i = 0; i < 4; i++) CP_ASYNC(sb + smoff[i], aptr[i] + k0, 16u);
#pragma unroll
            for (int i = 0; i < 4; i++) CP_ASYNC(sb + TILE_FLOATS * 4 + smoff[i], bptr[i] + k0, bsz[i]);
            CP_COMMIT();
            CP_WAIT(1);
        } else {
            CP_WAIT(0);
        }
        __syncthreads();

        const float* As = (const float*)(smem + (s & 1) * STAGE_BYTES);
        const float* Bs = As + TILE_FLOATS;
        const int gr = lane >> 2;
        const int gc = lane & 3;

#pragma unroll
        for (int kk = 0; kk < 4; kk++) {
            const int k0 = kk * 8;
            float a[4][4], b[4][2];
#pragma unroll
            for (int mt = 0; mt < 4; mt++) {
                int r0 = wm * 64 + mt * 16 + gr;
                a[mt][0] = As[r0 * LDT + k0 + gc];
                a[mt][1] = As[(r0 + 8) * LDT + k0 + gc];
                a[mt][2] = As[r0 * LDT + k0 + 4 + gc];
                a[mt][3] = As[(r0 + 8) * LDT + k0 + 4 + gc];
            }
#pragma unroll
            for (int nt = 0; nt < 4; nt++) {
                int c0 = wn * 32 + nt * 8 + gr;
                b[nt][0] = Bs[c0 * LDT + k0 + gc];
                b[nt][1] = Bs[c0 * LDT + k0 + 4 + gc];
            }
            if (PREC == 0) {
#pragma unroll
                for (int mt = 0; mt < 4; mt++)
#pragma unroll
                    for (int nt = 0; nt < 4; nt++)
                        mma_u(acc[mt][nt], (const uint32_t*)a[mt], (const uint32_t*)b[nt]);
            } else {
                uint32_t ah[4][4], al[4][4], bh[4][2], bl[4][2];
#pragma unroll
                for (int mt = 0; mt < 4; mt++)
#pragma unroll
                    for (int j = 0; j < 4; j++) split3(a[mt][j], ah[mt][j], al[mt][j]);
#pragma unroll
                for (int nt = 0; nt < 4; nt++)
#pragma unroll
                    for (int j = 0; j < 2; j++) split3(b[nt][j], bh[nt][j], bl[nt][j]);
#pragma unroll
                for (int mt = 0; mt < 4; mt++)
#pragma unroll
                    for (int nt = 0; nt < 4; nt++) {
                        mma_u(acc[mt][nt], ah[mt], bl[nt]);
                        mma_u(acc[mt][nt], al[mt], bh[nt]);
                        mma_u(acc[mt][nt], ah[mt], bh[nt]);
                    }
            }
        }
        __syncthreads();
    }

    const bool has_bias = (bias != nullptr);
    const int gr = lane >> 2;
    const int gc = lane & 3;
#pragma unroll
    for (int mt = 0; mt < 4; mt++) {
        int r0 = bm0 + wm * 64 + mt * 16 + gr;
#pragma unroll
        for (int nt = 0; nt < 4; nt++) {
            int c0 = bn0 + wn * 32 + nt * 8 + gc * 2;
            if (c0 < N) {
                float bx = has_bias ? bias[c0] : 0.f;
                float by = has_bias ? bias[c0 + 1] : 0.f;
                float v00 = acc[mt][nt][0] + bx, v01 = acc[mt][nt][1] + by;
                float v10 = acc[mt][nt][2] + bx, v11 = acc[mt][nt][3] + by;
                if (round_out) {
                    v00 = rtf32(v00); v01 = rtf32(v01);
                    v10 = rtf32(v10); v11 = rtf32(v11);
                }
                *(float2*)&C[(size_t)r0 * ldc + c0] = make_float2(v00, v01);
                *(float2*)&C[(size_t)(r0 + 8) * ldc + c0] = make_float2(v10, v11);
            }
        }
    }
}

// ---------------- round fp32 -> tf32(RN) elementwise ----------------
__global__ __launch_bounds__(256) void round_pass(
    const float* __restrict__ src, float* __restrict__ dst)
{
    int i = blockIdx.x * blockDim.x + threadIdx.x;
    float4 v = ((const float4*)src)[i];
    v.x = rtf32(v.x); v.y = rtf32(v.y); v.z = rtf32(v.z); v.w = rtf32(v.w);
    ((float4*)dst)[i] = v;
}

// ---------------- RoPE on q (with 1/sqrt(HD) scale) and k; outputs raw fp32 ----------------
__global__ __launch_bounds__(256) void rope_kernel(
    float* __restrict__ q, float* __restrict__ k,
    const float* __restrict__ cosb, const float* __restrict__ sinb)
{
    int idx = blockIdx.x * blockDim.x + threadIdx.x;
    int dh = idx & 63;
    int t = idx >> 6;
    int h = t & (NH - 1);
    int s = t >> 4;
    if (s >= S_LEN) return;

    float c1 = cosb[s * HDIM + dh];
    float s1 = sinb[s * HDIM + dh];
    float c2 = cosb[s * HDIM + dh + 64];
    float s2 = sinb[s * HDIM + dh + 64];

    size_t base = (size_t)s * (NH * HDIM) + h * HDIM + dh;
    const float sc = 0.08838834764831845f;  // 1/sqrt(128)

    float q1 = q[base], q2 = q[base + 64];
    q[base]      = (q1 * c1 - q2 * s1) * sc;
    q[base + 64] = (q2 * c2 + q1 * s2) * sc;

    float k1 = k[base], k2 = k[base + 64];
    k[base]      = k1 * c1 - k2 * s1;
    k[base + 64] = k2 * c2 + k1 * s2;
}

// ---------------- row softmax over 2048-wide rows, in place; rounds output ----------------
__global__ __launch_bounds__(256) void softmax_rows(float* __restrict__ L)
{
    __shared__ float red[8];
    float* p = L + (size_t)blockIdx.x * 2048;
    const int tid = threadIdx.x;
    const int wid = tid >> 5;
    const int lid = tid & 31;

    float4 a = ((const float4*)p)[tid];
    float4 b = ((const float4*)p)[tid + 256];

    float mx = fmaxf(fmaxf(fmaxf(a.x, a.y), fmaxf(a.z, a.w)),
                     fmaxf(fmaxf(b.x, b.y), fmaxf(b.z, b.w)));
#pragma unroll
    for (int m = 16; m > 0; m >>= 1) mx = fmaxf(mx, __shfl_xor_sync(~0u, mx, m));
    if (lid == 0) red[wid] = mx;
    __syncthreads();
    if (wid == 0) {
        float v = red[lid & 7];
#pragma unroll
        for (int m = 4; m > 0; m >>= 1) v = fmaxf(v, __shfl_xor_sync(~0u, v, m));
        if (lid == 0) red[0] = v;
    }
    __syncthreads();
    mx = red[0];
    __syncthreads();

    a.x = __expf(a.x - mx); a.y = __expf(a.y - mx); a.z = __expf(a.z - mx); a.w = __expf(a.w - mx);
    b.x = __expf(b.x - mx); b.y = __expf(b.y - mx); b.z = __expf(b.z - mx); b.w = __expf(b.w - mx);
    float sm = a.x + a.y + a.z + a.w + b.x + b.y + b.z + b.w;
#pragma unroll
    for (int m = 16; m > 0; m >>= 1) sm += __shfl_xor_sync(~0u, sm, m);
    if (lid == 0) red[wid] = sm;
    __syncthreads();
    if (wid == 0) {
        float v = red[lid & 7];
#pragma unroll
        for (int m = 4; m > 0; m >>= 1) v += __shfl_xor_sync(~0u, v, m);
        if (lid == 0) red[0] = v;
    }
    __syncthreads();
    const float inv = 1.f / red[0];

    a.x = rtf32(a.x * inv); a.y = rtf32(a.y * inv); a.z = rtf32(a.z * inv); a.w = rtf32(a.w * inv);
    b.x = rtf32(b.x * inv); b.y = rtf32(b.y * inv); b.z = rtf32(b.z * inv); b.w = rtf32(b.w * inv);
    ((float4*)p)[tid] = a;
    ((float4*)p)[tid + 256] = b;
}

// ---------------- 2048x2048 transpose (v -> v^T), rounds output ----------------
__global__ void transpose2048(const float* __restrict__ src, float* __restrict__ dst)
{
    __shared__ float t[32][33];
    int x = threadIdx.x, y = threadIdx.y;
    int r0 = blockIdx.y * 32, c0 = blockIdx.x * 32;
#pragma unroll
    for (int i = 0; i < 32; i += 8)
        t[y + i][x] = src[(size_t)(r0 + y + i) * 2048 + c0 + x];
    __syncthreads();
#pragma unroll
    for (int i = 0; i < 32; i += 8)
        dst[(size_t)(c0 + y + i) * 2048 + r0 + x] = rtf32(t[x][y + i]);
}

// ---------------- launch ----------------
extern "C" void kernel_launch(void* const* d_in, const int* in_sizes, int n_in,
                              void* d_out, int out_size)
{
    const float* x        = (const float*)d_in[0];
    const float* rope_cos = (const float*)d_in[1];
    const float* rope_sin = (const float*)d_in[2];
    const float* wq_down  = (const float*)d_in[3];
    const float* bq_down  = (const float*)d_in[4];
    const float* wq_up    = (const float*)d_in[5];
    const float* bq_up    = (const float*)d_in[6];
    const float* wkv_down = (const float*)d_in[7];
    const float* bkv_down = (const float*)d_in[8];
    const float* wk_up    = (const float*)d_in[9];
    const float* bk_up    = (const float*)d_in[10];
    const float* wv_up    = (const float*)d_in[11];
    const float* bv_up    = (const float*)d_in[12];
    const float* wo       = (const float*)d_in[13];
    const float* bo       = (const float*)d_in[14];
    float* out = (float*)d_out;

    float *cq, *ckv, *q, *k, *v, *vt, *attn, *logits;
    float *rx, *rwqd, *rwqu, *rwkvd, *rwku, *rwvu, *rwo;
    cudaGetSymbolAddress((void**)&cq,     g_cq);
    cudaGetSymbolAddress((void**)&ckv,    g_ckv);
    cudaGetSymbolAddress((void**)&q,      g_q);
    cudaGetSymbolAddress((void**)&k,      g_k);
    cudaGetSymbolAddress((void**)&v,      g_v);
    cudaGetSymbolAddress((void**)&vt,     g_vt);
    cudaGetSymbolAddress((void**)&attn,   g_attn);
    cudaGetSymbolAddress((void**)&logits, g_logits);
    cudaGetSymbolAddress((void**)&rx,     g_x);
    cudaGetSymbolAddress((void**)&rwqd,   g_wqd);
    cudaGetSymbolAddress((void**)&rwqu,   g_wqu);
    cudaGetSymbolAddress((void**)&rwkvd,  g_wkvd);
    cudaGetSymbolAddress((void**)&rwku,   g_wku);
    cudaGetSymbolAddress((void**)&rwvu,   g_wvu);
    cudaGetSymbolAddress((void**)&rwo,    g_wo);

    cudaFuncSetAttribute(gemm_mma<0>, cudaFuncAttributeMaxDynamicSharedMemorySize, GEMM_SMEM);
    cudaFuncSetAttribute(gemm_mma<1>, cudaFuncAttributeMaxDynamicSharedMemorySize, GEMM_SMEM);

    const long long SS = (long long)S_LEN * S_LEN;

    // pre-round external GEMM operands to tf32 (RN)
    round_pass<<<(S_LEN * D_MODEL) / 1024, 256>>>(x, rx);
    round_pass<<<(CQ_DIM * D_MODEL) / 1024, 256>>>(wq_down, rwqd);
    round_pass<<<(NH * HDIM * CQ_DIM) / 1024, 256>>>(wq_up, rwqu);
    round_pass<<<(CKV_DIM * D_MODEL) / 1024, 256>>>(wkv_down, rwkvd);
    round_pass<<<(NH * HDIM * CKV_DIM) / 1024, 256>>>(wk_up, rwku);
    round_pass<<<(NH * HDIM * CKV_DIM) / 1024, 256>>>(wv_up, rwvu);
    round_pass<<<(D_MODEL * NH * HDIM) / 1024, 256>>>(wo, rwo);

    // c_q = x @ wq_down^T + b            [2048, 96]  (rounded out)
    gemm_mma<0><<<dim3(1, 16, 1), 256, GEMM_SMEM>>>(
        rx, rwqd, bq_down, cq, CQ_DIM, D_MODEL, D_MODEL, D_MODEL, CQ_DIM, 0, 0, 0, 1);
    // q = c_q @ wq_up^T + b              [2048, 2048]
    gemm_mma<0><<<dim3(16, 16, 1), 256, GEMM_SMEM>>>(
        cq, rwqu, bq_up, q, 2048, CQ_DIM, CQ_DIM, CQ_DIM, 2048, 0, 0, 0, 0);
    // c_kv = x @ wkv_down^T + b          [2048, 512] (rounded out)
    gemm_mma<0><<<dim3(4, 16, 1), 256, GEMM_SMEM>>>(
        rx, rwkvd, bkv_down, ckv, CKV_DIM, D_MODEL, D_MODEL, D_MODEL, CKV_DIM, 0, 0, 0, 1);
    // k = c_kv @ wk_up^T + b             [2048, 2048]
    gemm_mma<0><<<dim3(16, 16, 1), 256, GEMM_SMEM>>>(
        ckv, rwku, bk_up, k, 2048, CKV_DIM, CKV_DIM, CKV_DIM, 2048, 0, 0, 0, 0);
    // v = c_kv @ wv_up^T + b             [2048, 2048]
    gemm_mma<0><<<dim3(16, 16, 1), 256, GEMM_SMEM>>>(
        ckv, rwvu, bv_up, v, 2048, CKV_DIM, CKV_DIM, CKV_DIM, 2048, 0, 0, 0, 0);

    // rope(q) * 1/sqrt(HD), rope(k) — raw fp32 outputs (logits GEMM is tf32x3)
    rope_kernel<<<(S_LEN * NH * 64) / 256, 256>>>(q, k, rope_cos, rope_sin);

    // logits[h] = Q_h @ K_h^T  — tf32x3 (fp32-accurate)
    gemm_mma<1><<<dim3(16, 16, NH), 256, GEMM_SMEM>>>(
        q, k, nullptr, logits, 2048, HDIM, 2048, 2048, 2048,
        HDIM, HDIM, SS, 0);

    // softmax rows (rounds output to tf32)
    softmax_rows<<<NH * S_LEN, 256>>>(logits);

    // v^T (rounds output)
    transpose2048<<<dim3(64, 64), dim3(32, 8)>>>(v, vt);

    // attn per head: M=2048, N=128, K=2048 (rounded out)
    gemm_mma<0><<<dim3(1, 16, NH), 256, GEMM_SMEM>>>(
        logits, vt, nullptr, attn, HDIM, 2048, 2048, 2048, 2048,
        SS, (long long)HDIM * 2048, HDIM, 1);

    // out = attn @ wo^T + bo             [2048, 2048] (full fp32 output)
    gemm_mma<0><<<dim3(16, 16, 1), 256, GEMM_SMEM>>>(
        attn, rwo, bo, out, 2048, 2048, 2048, 2048, 2048, 0, 0, 0, 0);
}